// round 17
// baseline (speedup 1.0000x reference)
#include <cuda_runtime.h>
#include <cuda_fp16.h>
#include <cstdint>

// Problem constants
#define B_ 2
#define T_ 4096
#define C_ 2048
#define H_ 16
#define D_ 32

// ---------------------------------------------------------------------------
// Ext-fp16 tile formats (sw128-swizzled, 128B physical rows):
//  FULL tile (16KB/128rows): row r, ext col c in [0,64): c<32 = hi of d=c,
//    c>=32 = lo of d=c-32, at byte sw128(r*128 + c*2).
//  HI-ONLY tile: same addressing, lo half never written/read (holes).
// All products pure hi x hi (2 MMAs per 16x16 frag-pair); dropped terms
// are each ~2^-12 relative and compose ~RSS (measured rounds 11-14).
// ---------------------------------------------------------------------------
__device__ __align__(1024) char g_xext [(size_t)64 * 64 * 16384];  // [rowTile][kStep] hi-only
__device__ __align__(1024) char g_wqext[(size_t)4  * 64 * 16384];  // [nTile][kStep] full (hi read)
__device__ __align__(1024) char g_kwext[(size_t)64 * 6144];        // [kStep] 48 rows, full (hi read)
__device__ __align__(1024) char g_qext [(size_t)64 * 16 * 16384];  // [qTile][head] hi-only
__device__ __align__(1024) char g_kext [(size_t)64 * 16384];       // [kTile] hi-only
__device__ __align__(1024) float g_w[(size_t)B_ * T_ * H_];        // [8192][16]

// ===========================================================================
// Helpers (base sm_103-safe: ldmatrix + mma.sync + cp.async)
// ===========================================================================
__device__ __forceinline__ uint32_t smem_u32(const void* p) {
    uint32_t a;
    asm("{ .reg .u64 t; cvta.to.shared.u64 t, %1; cvt.u32.u64 %0, t; }"
        : "=r"(a) : "l"(p));
    return a;
}

__device__ __forceinline__ uint32_t sw128(uint32_t o) { return o ^ ((o >> 3) & 0x70); }

__device__ __forceinline__ void ldsm4(uint32_t* r, uint32_t a) {
    asm volatile("ldmatrix.sync.aligned.m8n8.x4.shared.b16 {%0,%1,%2,%3}, [%4];"
                 : "=r"(r[0]), "=r"(r[1]), "=r"(r[2]), "=r"(r[3]) : "r"(a));
}

__device__ __forceinline__ void mma_f16(float* d, const uint32_t* a, const uint32_t* b) {
    asm volatile(
        "mma.sync.aligned.m16n8k16.row.col.f32.f16.f16.f32 "
        "{%0,%1,%2,%3}, {%4,%5,%6,%7}, {%8,%9}, {%0,%1,%2,%3};"
        : "+f"(d[0]), "+f"(d[1]), "+f"(d[2]), "+f"(d[3])
        : "r"(a[0]), "r"(a[1]), "r"(a[2]), "r"(a[3]), "r"(b[0]), "r"(b[1]));
}

// Non-accumulating variant: d = a*b + 0 (c = constant zeros, no init MOVs).
__device__ __forceinline__ void mma_f16_z(float* d, const uint32_t* a, const uint32_t* b) {
    asm volatile(
        "mma.sync.aligned.m16n8k16.row.col.f32.f16.f16.f32 "
        "{%0,%1,%2,%3}, {%4,%5,%6,%7}, {%8,%9}, {%10,%10,%10,%10};"
        : "=f"(d[0]), "=f"(d[1]), "=f"(d[2]), "=f"(d[3])
        : "r"(a[0]), "r"(a[1]), "r"(a[2]), "r"(a[3]), "r"(b[0]), "r"(b[1]),
          "f"(0.f));
}

__device__ __forceinline__ void cp16(uint32_t s, const void* g) {
    asm volatile("cp.async.cg.shared.global [%0], [%1], 16;" :: "r"(s), "l"(g));
}
#define CP_COMMIT() asm volatile("cp.async.commit_group;" ::: "memory")
#define CP_WAIT(n)  asm volatile("cp.async.wait_group %0;" :: "n"(n) : "memory")

__device__ __forceinline__ uint32_t pack2h(float x, float y) {
    __half h0 = __float2half_rn(x), h1 = __float2half_rn(y);
    return ((uint32_t)__half_as_ushort(h1) << 16) | (uint32_t)__half_as_ushort(h0);
}

// split two f32 into packed fp16 hi-pair and fp16 lo-pair (lo = residual)
__device__ __forceinline__ void split2(float v0, float v1, uint32_t& hi, uint32_t& lo) {
    __half h0 = __float2half_rn(v0), h1 = __float2half_rn(v1);
    hi = ((uint32_t)__half_as_ushort(h1) << 16) | (uint32_t)__half_as_ushort(h0);
    __half g0 = __float2half_rn(v0 - __half2float(h0));
    __half g1 = __float2half_rn(v1 - __half2float(h1));
    lo = ((uint32_t)__half_as_ushort(g1) << 16) | (uint32_t)__half_as_ushort(g0);
}

// 8 consecutive f32 -> full tile: 16B hi + 16B lo stores
__device__ __forceinline__ void cvt_store8(char* tile, uint32_t base_off,
                                           float4 a, float4 b) {
    uint4 hi, lo;
    split2(a.x, a.y, hi.x, lo.x);
    split2(a.z, a.w, hi.y, lo.y);
    split2(b.x, b.y, hi.z, lo.z);
    split2(b.z, b.w, hi.w, lo.w);
    *(uint4*)(tile + sw128(base_off))      = hi;
    *(uint4*)(tile + sw128(base_off + 64)) = lo;
}

// 8 consecutive f32 -> hi-only tile: single 16B store
__device__ __forceinline__ void cvt_store8_hi(char* tile, uint32_t base_off,
                                              float4 a, float4 b) {
    uint4 hi;
    hi.x = pack2h(a.x, a.y);
    hi.y = pack2h(a.z, a.w);
    hi.z = pack2h(b.x, b.y);
    hi.w = pack2h(b.z, b.w);
    *(uint4*)(tile + sw128(base_off)) = hi;
}

// Pure hi x hi, EIGHT independent chains (2 mt x 4), accumulating.
// Dependent MMAs (p=0 -> p=1 on same chain) are 8 issues apart.
__device__ __forceinline__ void mma_hh_x8(float acc[2][4][4],
                                          const uint32_t af[2][2][4],
                                          const uint32_t b0[2][4],
                                          const uint32_t b1[2][4]) {
#pragma unroll
    for (int p = 0; p < 2; p++)
#pragma unroll
        for (int mt = 0; mt < 2; mt++) {
            mma_f16(acc[mt][0], af[mt][p], &b0[p][0]);
            mma_f16(acc[mt][1], af[mt][p], &b0[p][2]);
            mma_f16(acc[mt][2], af[mt][p], &b1[p][0]);
            mma_f16(acc[mt][3], af[mt][p], &b1[p][2]);
        }
}

// Same, but p=0 writes fresh (zero-c) — no accumulator init needed.
__device__ __forceinline__ void mma_hh_x8_z(float s[2][4][4],
                                            const uint32_t af[2][2][4],
                                            const uint32_t b0[2][4],
                                            const uint32_t b1[2][4]) {
#pragma unroll
    for (int mt = 0; mt < 2; mt++) {
        mma_f16_z(s[mt][0], af[mt][0], &b0[0][0]);
        mma_f16_z(s[mt][1], af[mt][0], &b0[0][2]);
        mma_f16_z(s[mt][2], af[mt][0], &b1[0][0]);
        mma_f16_z(s[mt][3], af[mt][0], &b1[0][2]);
    }
#pragma unroll
    for (int mt = 0; mt < 2; mt++) {
        mma_f16(s[mt][0], af[mt][1], &b0[1][0]);
        mma_f16(s[mt][1], af[mt][1], &b0[1][2]);
        mma_f16(s[mt][2], af[mt][1], &b1[1][0]);
        mma_f16(s[mt][3], af[mt][1], &b1[1][2]);
    }
}

// ===========================================================================
// Merged conversion pass.
// Linear grid: [0,4096) X tiles (hi-only), [4096,4352) Wq (full),
// [4352,4416) WkWw (full).
// ===========================================================================
__global__ void __launch_bounds__(256)
cvt_all_kernel(const float* __restrict__ X, const float* __restrict__ Wq,
               const float* __restrict__ Wk, const float* __restrict__ Ww)
{
    const int bid = blockIdx.x;
    const int tid = threadIdx.x;

    if (bid < 4096) {
        const int rowTile = bid >> 6, kStep = bid & 63;
        const float* srcb = X + (size_t)(rowTile * 128) * C_ + kStep * 32;
        char* dst = g_xext + ((size_t)rowTile * 64 + kStep) * 16384;
#pragma unroll
        for (int j = 0; j < 2; j++) {
            const int idx = tid + j * 256;          // 0..511
            const int r = idx >> 2, c8 = (idx & 3) * 8;
            const float* s = srcb + (size_t)r * C_ + c8;
            cvt_store8_hi(dst, (uint32_t)(r * 128 + c8 * 2),
                          *(const float4*)s, *(const float4*)(s + 4));
        }
    } else if (bid < 4352) {
        const int t = bid - 4096;
        const int nTile = t >> 6, kStep = t & 63;
        const float* srcb = Wq + (size_t)(nTile * 128) * C_ + kStep * 32;
        char* dst = g_wqext + ((size_t)nTile * 64 + kStep) * 16384;
#pragma unroll
        for (int j = 0; j < 2; j++) {
            const int idx = tid + j * 256;
            const int r = idx >> 2, c8 = (idx & 3) * 8;
            const float* s = srcb + (size_t)r * C_ + c8;
            cvt_store8(dst, (uint32_t)(r * 128 + c8 * 2),
                       *(const float4*)s, *(const float4*)(s + 4));
        }
    } else {
        const int kStep = bid - 4352;
        if (tid >= 192) return;                     // 48 rows * 4 chunks
        const int r = tid >> 2, c8 = (tid & 3) * 8;
        const float* s = (r < 32) ? (Wk + (size_t)r * C_ + kStep * 32 + c8)
                                  : (Ww + (size_t)(r - 32) * C_ + kStep * 32 + c8);
        char* dst = g_kwext + (size_t)kStep * 6144;
        cvt_store8(dst, (uint32_t)(r * 128 + c8 * 2),
                   *(const float4*)s, *(const float4*)(s + 4));
    }
}

// ===========================================================================
// Unified projection kernel. grid (9, 64):
//   nT in 0..7 : Q-proj, 64 output cols (nT*64..), writes g_qext (hi-only)
//   nT == 8    : K+W proj (48 cols from g_kwext), writes g_kext (hi) + g_w
// CTA: 128(m) x 64(n), 256 threads, 8 warps 4(m) x 2(n), warp tile 32x32.
// 4-deep k=32 pipeline (4 x 24KB buffers, 3 cp groups in flight), 64 iters,
// 2 CTAs/SM.  Pure hi x hi; 8-chain interleaved MMA schedule.
// ===========================================================================
__global__ void __launch_bounds__(256, 2)
proj_mma_kernel()
{
    extern __shared__ char dsm_raw[];
    char* dsm = (char*)(((uintptr_t)dsm_raw + 1023) & ~(uintptr_t)1023);

    const int tid  = threadIdx.x;
    const int wid  = tid >> 5;
    const int lane = tid & 31;
    const int nT    = blockIdx.x;           // 0..8
    const int mTile = blockIdx.y;           // 0..63
    const int m0 = (wid & 3) * 32;
    const int n0 = (wid >> 2) * 32;
    const bool iskw = (nT == 8);

    const char* xsrc = g_xext + (size_t)mTile * 64 * 16384;
    const char* wsrc = iskw ? g_kwext
                            : g_wqext + (size_t)(nT >> 1) * 64 * 16384 + (nT & 1) * 8192;
    const uint32_t wstep   = iskw ? 6144u : 16384u;  // bytes per k-step in gmem
    const int      wchunks = iskw ? 192 : 256;       // hi 16B chunks per k-step

    uint32_t sbase[4];
#pragma unroll
    for (int s = 0; s < 4; s++) sbase[s] = smem_u32(dsm + s * 24576);

    uint32_t aoff[2][2], boff[2][2];
    {
        const int arow = lane & 15, aseg = lane >> 4;
        const int brow = (lane & 7) + ((lane & 16) >> 1);
        const int bseg = (lane >> 3) & 1;
#pragma unroll
        for (int t = 0; t < 2; t++) {
#pragma unroll
            for (int ks = 0; ks < 2; ks++) {     // hi frags only, both sides
                aoff[t][ks] = sw128((uint32_t)((m0 + t * 16 + arow) * 128 +
                                               ks * 32 + aseg * 16));
                boff[t][ks] = 16384u + sw128((uint32_t)((n0 + t * 16 + brow) * 128 +
                                                        ks * 32 + bseg * 16));
            }
        }
    }

    // issue one k=32 stage into buffer stage&3; hi chunks only
    auto issue_stage = [&](int stage) {
        const uint32_t sb = sbase[stage & 3];
        const size_t ks = (size_t)stage;
#pragma unroll
        for (int j = 0; j < 2; j++) {
            const int idx = tid + j * 256;
            const uint32_t off = sw128((uint32_t)((idx >> 2) * 128 + (idx & 3) * 16));
            cp16(sb + off, xsrc + ks * 16384 + off);
        }
        if (tid < wchunks) {
            const uint32_t off = sw128((uint32_t)((tid >> 2) * 128 + (tid & 3) * 16));
            cp16(sb + 16384u + off, wsrc + ks * wstep + off);
        }
    };

    // prologue: stages 0,1,2 (three groups in flight)
#pragma unroll
    for (int s = 0; s < 3; s++) {
        issue_stage(s);
        CP_COMMIT();
    }

    float acc[2][4][4];
#pragma unroll
    for (int mt = 0; mt < 2; mt++)
#pragma unroll
        for (int nt = 0; nt < 4; nt++)
#pragma unroll
            for (int c = 0; c < 4; c++) acc[mt][nt][c] = 0.f;

#pragma unroll 1
    for (int it = 0; it < 64; it++) {
        CP_WAIT(2);          // all but newest 2 groups done => stage it done
        __syncthreads();     // data visible + all warps done with buf (it+3)&3
        if (it + 3 < 64) issue_stage(it + 3);
        CP_COMMIT();         // unconditional: keeps group count uniform

        const uint32_t cb = sbase[it & 3];
        uint32_t bfr[2][2][4];
#pragma unroll
        for (int ntp = 0; ntp < 2; ntp++)
#pragma unroll
            for (int ks = 0; ks < 2; ks++)
                ldsm4(bfr[ntp][ks], cb + boff[ntp][ks]);

        uint32_t af[2][2][4];
#pragma unroll
        for (int mt = 0; mt < 2; mt++)
#pragma unroll
            for (int ks = 0; ks < 2; ks++)
                ldsm4(af[mt][ks], cb + aoff[mt][ks]);

        mma_hh_x8(acc, af, bfr[0], bfr[1]);
    }

    // epilogue
#pragma unroll
    for (int mt = 0; mt < 2; mt++)
#pragma unroll
        for (int rp = 0; rp < 2; rp++) {
            const int r = m0 + mt * 16 + (lane >> 2) + rp * 8;
#pragma unroll
            for (int nt = 0; nt < 4; nt++) {
                const int colL = n0 + nt * 8 + (lane & 3) * 2;
                const float v0 = acc[mt][nt][rp * 2];
                const float v1 = acc[mt][nt][rp * 2 + 1];
                if (!iskw) {
                    const int col = nT * 64 + colL;
                    const int head = col >> 5;
                    const int d = col & 31;
                    char* dst = g_qext + ((size_t)mTile * 16 + head) * 16384;
                    *(uint32_t*)(dst + sw128((uint32_t)(r * 128 + d * 2))) =
                        pack2h(v0, v1);                       // hi-only
                } else if (colL < 32) {
                    char* dst = g_kext + (size_t)mTile * 16384;
                    *(uint32_t*)(dst + sw128((uint32_t)(r * 128 + colL * 2))) =
                        pack2h(v0, v1);                       // hi-only
                } else if (colL < 48) {
                    *(float2*)(g_w + (size_t)(mTile * 128 + r) * H_ + (colL - 32)) =
                        make_float2(v0, v1);
                }
            }
        }
}

// ===========================================================================
// Fused scores+importance: out[b,q,k] = sum_h w[b,q,h]*relu(dot(q,k))
// TRANSPOSED TILING: CTA = 64(q) x 128(k), 256 threads, 8 warps 2(m)x4(n),
// warp tile 32x32, 2 CTAs/SM.  K 128-row hi tile resident; Q 64-row half
// tiles streamed 2 heads per stage (3 x 16KB ring).
// Product = q_hi * k_hi, 8-chain interleaved schedule, zero-c first step.
// ===========================================================================
__global__ void __launch_bounds__(256, 2)
fused_mma_kernel(float* __restrict__ out)
{
    extern __shared__ char dsm_raw[];
    char* dsm = (char*)(((uintptr_t)dsm_raw + 1023) & ~(uintptr_t)1023);
    char* Ks   = dsm;                   // 16KB (128 rows, hi holes)
    char* Qb   = dsm + 16384;           // 3 x 16KB (2 x 64-row head halves)
    float* w_s = (float*)(dsm + 65536); // 4KB (64 rows x 16)

    const int tid  = threadIdx.x;
    const int wid  = tid >> 5;
    const int lane = tid & 31;
    const int b  = blockIdx.z;
    const int kT = blockIdx.x;          // 0..31 (128-col k tiles)
    const int qT = blockIdx.y;          // 0..63 (64-row q tiles)
    const int q0 = qT * 64;
    const int k0 = kT * 128;
    const int m0 = (wid & 1) * 32;      // 2 warps in m (64 rows)
    const int n0 = (wid >> 1) * 32;     // 4 warps in n (128 cols)

    const char* qsrc = g_qext + (size_t)(b * 32 + (qT >> 1)) * 16 * 16384
                             + (size_t)(qT & 1) * 8192;   // + h*16384 per head
    const char* ksrc = g_kext + (size_t)(b * 32 + kT) * 16384;
    const float* wsrc = g_w + (size_t)(b * T_ + q0) * H_;

    const uint32_t ksb = smem_u32(Ks);
    const uint32_t wsb_smem = smem_u32(w_s);
    uint32_t qbase[3];
#pragma unroll
    for (int s = 0; s < 3; s++) qbase[s] = smem_u32(Qb + s * 16384);

    // Q head-pair loader: 512 hi chunks (2 heads x 64 rows x 4 chunks)
    auto load_qpair = [&](uint32_t qb, int p) {
#pragma unroll
        for (int j = 0; j < 2; j++) {
            const int idx = tid + j * 256;          // 0..511
            const int hh = idx >> 8;                // 0/1
            const int rem = idx & 255;              // row*4 + chunk
            const uint32_t off = sw128((uint32_t)((rem >> 2) * 128 + (rem & 3) * 16));
            cp16(qb + (uint32_t)hh * 8192u + off,
                 qsrc + (size_t)(p * 2 + hh) * 16384 + off);
        }
    };

    // prologue: G0 = {K hi, w, headpair 0}, G1 = {headpair 1}
#pragma unroll
    for (int j = 0; j < 2; j++) {
        const int idx = tid + j * 256;              // 0..511 K hi chunks
        const uint32_t off = sw128((uint32_t)((idx >> 2) * 128 + (idx & 3) * 16));
        cp16(ksb + off, ksrc + off);
    }
    cp16(wsb_smem + (uint32_t)tid * 16, (const char*)wsrc + (uint32_t)tid * 16);
    load_qpair(qbase[0], 0);
    CP_COMMIT();
    load_qpair(qbase[1], 1);
    CP_COMMIT();

    uint32_t aoff[2][2];
    uint32_t baddr[2][2];
    {
        const int arow = lane & 15, aseg = lane >> 4;
        const int brow = (lane & 7) + ((lane & 16) >> 1);
        const int bseg = (lane >> 3) & 1;
#pragma unroll
        for (int t = 0; t < 2; t++) {
#pragma unroll
            for (int ks = 0; ks < 2; ks++) {     // hi frags only, both sides
                aoff[t][ks] = sw128((uint32_t)((m0 + t * 16 + arow) * 128 +
                                               ks * 32 + aseg * 16));
                baddr[t][ks] = ksb + sw128((uint32_t)((n0 + t * 16 + brow) * 128 +
                                                      ks * 32 + bseg * 16));
            }
        }
    }

    float acc[2][4][4];
#pragma unroll
    for (int mt = 0; mt < 2; mt++)
#pragma unroll
        for (int nt = 0; nt < 4; nt++)
#pragma unroll
            for (int c = 0; c < 4; c++) acc[mt][nt][c] = 0.f;

    CP_WAIT(1);       // G0 done: K, w, headpair 0
    __syncthreads();

    // K hi fragments register-resident (this warp's 32 n-cols of 128)
    uint32_t bfr[2][2][4];
#pragma unroll
    for (int ntp = 0; ntp < 2; ntp++)
#pragma unroll
        for (int ks = 0; ks < 2; ks++) ldsm4(bfr[ntp][ks], baddr[ntp][ks]);

    const int wrow0 = m0 + (lane >> 2);

#pragma unroll 1
    for (int p = 0; p < H_ / 2; p++) {      // head pairs
        if (p > 0) {
            if (p == H_ / 2 - 1) CP_WAIT(0); else CP_WAIT(1);
            __syncthreads();
        }
        if (p + 2 < H_ / 2)
            load_qpair(qbase[(p + 2) % 3], p + 2);
        CP_COMMIT();

        const uint32_t qb = qbase[p % 3];
#pragma unroll
        for (int hh = 0; hh < 2; hh++) {
            const int h = p * 2 + hh;
            const uint32_t qbh = qb + (uint32_t)hh * 8192u;

            uint32_t af[2][2][4];
#pragma unroll
            for (int mt = 0; mt < 2; mt++)
#pragma unroll
                for (int ks = 0; ks < 2; ks++)
                    ldsm4(af[mt][ks], qbh + aoff[mt][ks]);

            float s[2][4][4];
            mma_hh_x8_z(s, af, bfr[0], bfr[1]);

#pragma unroll
            for (int mt = 0; mt < 2; mt++) {
                const float wv0 = w_s[(wrow0 + mt * 16) * H_ + h];
                const float wv1 = w_s[(wrow0 + mt * 16 + 8) * H_ + h];
#pragma unroll
                for (int nt = 0; nt < 4; nt++) {
                    float* a = acc[mt][nt];
                    const float* sv = s[mt][nt];
                    a[0] += wv0 * fmaxf(sv[0], 0.f);
                    a[1] += wv0 * fmaxf(sv[1], 0.f);
                    a[2] += wv1 * fmaxf(sv[2], 0.f);
                    a[3] += wv1 * fmaxf(sv[3], 0.f);
                }
            }
        }
    }

    // epilogue: 64 rows x 128 cols
#pragma unroll
    for (int mt = 0; mt < 2; mt++)
#pragma unroll
        for (int rp = 0; rp < 2; rp++) {
            const int row = q0 + m0 + mt * 16 + (lane >> 2) + rp * 8;
            float* op = out + (size_t)(b * T_ + row) * T_ + k0 + n0 + (lane & 3) * 2;
#pragma unroll
            for (int nt = 0; nt < 4; nt++)
                *(float2*)(op + nt * 8) =
                    make_float2(acc[mt][nt][rp * 2], acc[mt][nt][rp * 2 + 1]);
        }
}

// ===========================================================================
extern "C" void kernel_launch(void* const* d_in, const int* in_sizes, int n_in,
                              void* d_out, int out_size)
{
    (void)in_sizes; (void)n_in; (void)out_size;
    const float* x  = (const float*)d_in[0];
    const float* Wq = (const float*)d_in[1];
    const float* Wk = (const float*)d_in[2];
    const float* Ww = (const float*)d_in[3];
    float* out = (float*)d_out;

    static bool attr_done = false;
    if (!attr_done) {
        cudaFuncSetAttribute(proj_mma_kernel,
                             cudaFuncAttributeMaxDynamicSharedMemorySize, 99328);
        cudaFuncSetAttribute(fused_mma_kernel,
                             cudaFuncAttributeMaxDynamicSharedMemorySize, 70656);
        attr_done = true;
    }

    cvt_all_kernel<<<4416, 256>>>(x, Wq, Wk, Ww);
    proj_mma_kernel<<<dim3(9, 64), 256, 99328>>>();
    fused_mma_kernel<<<dim3(T_ / 128, T_ / 64, B_), 256, 70656>>>(out);
}